// round 15
// baseline (speedup 1.0000x reference)
#include <cuda_runtime.h>
#include <stdint.h>

// Problem constants (fixed: IM_SIZE=(1080,1920), SCALE=(0.25,0.25), B=8, C=3)
#define H_IN 1080
#define W_IN 1920
#define OH   270
#define OW   480
#define BC   24
#define MAX_TAPS 20
#define WQ   (W_IN / 4)

// Fused single kernel: vertical resample of one row -> skewed smem ->
// horizontal gather -> output. No global mid (saves 100 MB round-trip).
//
// Block: 480 threads (t == wq for loads, t == ow for gather), R_F rows.
// Per row r: write vert result float4 into buf[r&1] (skewed scalar STS),
// ONE __syncthreads, then issue next row's 16 vertical LDG.128 (latency
// hidden under...) the 16-LDS scalar skewed gather (R11's proven pattern).
// Two-buffer + single barrier correctness: a warp's gather-r LDS are issued
// before it reaches sync@r+1; any other warp's store to buf[r&1] happens
// after sync@r+2 > sync@r+1, so no overwrite hazard (same scheme as R11).
// grid: (OH/R_F, BC), block 480, 2 blocks/SM via launch_bounds.
#define R_F 5                          // 270 % 5 == 0 -> grid.x = 54
#define SROW_SZ (W_IN + W_IN / 32)     // 1980 floats, skewed row buffer

template <int TAPS>
__global__ void __launch_bounds__(480, 2)
fused_resize(const float* __restrict__ x,
             const float* __restrict__ w_h,
             const int*   __restrict__ idx_h,
             const float* __restrict__ w_w,
             const int*   __restrict__ idx_w,
             float* __restrict__ out,
             int th_rt, int tw_rt)
{
    const int th = (TAPS > 0) ? TAPS : th_rt;
    const int tw = (TAPS > 0) ? TAPS : tw_rt;

    __shared__ float buf[2][SROW_SZ];
    __shared__ float swv[R_F * MAX_TAPS];
    __shared__ int   srv[R_F * MAX_TAPS];

    const int t   = threadIdx.x;       // == wq == ow (both 480 wide)
    const int bc  = blockIdx.y;
    const int oh0 = blockIdx.x * R_F;

    // Stage vertical weights/rows for this block's R_F output rows
    for (int i = t; i < R_F * th; i += 480) {
        const int g = i / th;
        const int p = i - g * th;
        swv[i] = w_h[(oh0 + g) * th + p];
        int r = idx_h[(oh0 + g) * th + p];
        r = (r < 0) ? 0 : (r > H_IN - 1 ? H_IN - 1 : r);
        srv[i] = r;
    }

    // Registerized horizontal weights + pre-skewed positions (R11 pattern)
    float wreg[(TAPS > 0) ? TAPS : MAX_TAPS];
    int   preg[(TAPS > 0) ? TAPS : MAX_TAPS];
#pragma unroll
    for (int p = 0; p < ((TAPS > 0) ? TAPS : MAX_TAPS); ++p) {
        if (TAPS == 0 && p >= tw) break;
        wreg[p] = w_w[t * tw + p];
        int c = idx_w[t * tw + p];
        c = (c < 0) ? 0 : (c > W_IN - 1 ? W_IN - 1 : c);
        preg[p] = c + (c >> 5);
    }

    __syncthreads();                   // swv/srv visible

    const float4* xcol = (const float4*)x + (size_t)bc * H_IN * WQ + t;
    const int c0   = t * 4;
    const int base = c0 + (c0 >> 5);   // skewed float4 slot (stays in one 32-group)

    // Vertical resample of output row g for this thread's float4 column.
    auto vert = [&](int g) -> float4 {
        float4 a = make_float4(0.f, 0.f, 0.f, 0.f);
#pragma unroll
        for (int p = 0; p < ((TAPS > 0) ? TAPS : MAX_TAPS); ++p) {
            if (TAPS == 0 && p >= th) break;
            const float  w = swv[g * th + p];
            const float4 v = __ldg(xcol + (size_t)srv[g * th + p] * WQ);
            a.x += w * v.x; a.y += w * v.y; a.z += w * v.z; a.w += w * v.w;
        }
        return a;
    };

    float4 acc = vert(0);

#pragma unroll
    for (int r = 0; r < R_F; ++r) {
        float* cur = buf[r & 1];

        cur[base + 0] = acc.x;         // skewed scalar STS, conflict-free
        cur[base + 1] = acc.y;
        cur[base + 2] = acc.z;
        cur[base + 3] = acc.w;
        __syncthreads();               // stage visible; fences gathers from r-2

        // Next row's vertical loads issued BEFORE the gather: their DRAM
        // latency hides under the 16-LDS gather + co-resident block.
        float4 nxt = make_float4(0.f, 0.f, 0.f, 0.f);
        if (r + 1 < R_F)
            nxt = vert(r + 1);

        // Horizontal gather: 16 scalar skewed LDS (1 phase each), split accs
        float a0 = 0.f, a1 = 0.f;
#pragma unroll
        for (int p = 0; p < ((TAPS > 0) ? TAPS : MAX_TAPS); p += 2) {
            if (TAPS == 0 && p >= tw) break;
            a0 += wreg[p] * cur[preg[p]];
            if (TAPS > 0 || p + 1 < tw)
                a1 += wreg[p + 1] * cur[preg[p + 1]];
        }
        out[((size_t)bc * OH + oh0 + r) * OW + t] = a0 + a1;

        acc = nxt;
    }
}

// ---------------------------------------------------------------------------
// kernel_launch
// inputs: x(f32), w_h(f32), idx_h(i32), w_w(f32), idx_w(i32); output f32
// ---------------------------------------------------------------------------
extern "C" void kernel_launch(void* const* d_in, const int* in_sizes, int n_in,
                              void* d_out, int out_size)
{
    const float* x     = (const float*)d_in[0];
    const float* w_h   = (const float*)d_in[1];
    const int*   idx_h = (const int*)d_in[2];
    const float* w_w   = (const float*)d_in[3];
    const int*   idx_w = (const int*)d_in[4];
    float*       out   = (float*)d_out;

    int taps_h = in_sizes[1] / OH;
    int taps_w = in_sizes[3] / OW;
    if (taps_h > MAX_TAPS) taps_h = MAX_TAPS;
    if (taps_w > MAX_TAPS) taps_w = MAX_TAPS;

    dim3 grid(OH / R_F, BC);           // (54, 24) = 1296 blocks
    if (taps_h == 16 && taps_w == 16)
        fused_resize<16><<<grid, 480>>>(x, w_h, idx_h, w_w, idx_w, out,
                                        taps_h, taps_w);
    else
        fused_resize<0><<<grid, 480>>>(x, w_h, idx_h, w_w, idx_w, out,
                                       taps_h, taps_w);
}

// round 16
// speedup vs baseline: 1.2638x; 1.2638x over previous
#include <cuda_runtime.h>
#include <stdint.h>

// Problem constants (fixed: IM_SIZE=(1080,1920), SCALE=(0.25,0.25), B=8, C=3)
#define H_IN 1080
#define W_IN 1920
#define OH   270
#define OW   480
#define BC   24
#define MAX_TAPS 20
#define WQ   (W_IN / 4)

// Scratch: vertical-resized intermediate [BC, OH, W_IN] (~49.8 MB)
__device__ float g_mid[(size_t)BC * OH * W_IN];

// ---------------------------------------------------------------------------
// Pass 1: vertical resample (R11 exact — proven ~48-52us, DRAM-floor bound).
// grid: (WQ/128, OH, BC), block: 128
// ---------------------------------------------------------------------------
template <int TAPS>
__global__ void __launch_bounds__(128)
pass1_vert(const float* __restrict__ x,
           const float* __restrict__ w_h,
           const int* __restrict__ idx_h,
           int taps_rt)
{
    const int taps = (TAPS > 0) ? TAPS : taps_rt;
    __shared__ float sw[MAX_TAPS];
    __shared__ int   srow[MAX_TAPS];

    const int oh = blockIdx.y;
    const int bc = blockIdx.z;
    const int t  = threadIdx.x;

    if (t < taps) {
        sw[t] = w_h[oh * taps + t];
        int r = idx_h[oh * taps + t];
        r = (r < 0) ? 0 : (r > H_IN - 1 ? H_IN - 1 : r);
        srow[t] = r;
    }
    __syncthreads();

    const int wq = blockIdx.x * 128 + t;
    if (wq >= WQ) return;

    const float4* xin = (const float4*)x + (size_t)bc * H_IN * WQ + wq;

    float4 acc = make_float4(0.f, 0.f, 0.f, 0.f);
#pragma unroll
    for (int p = 0; p < ((TAPS > 0) ? TAPS : MAX_TAPS); ++p) {
        if (TAPS == 0 && p >= taps) break;
        const float  w = sw[p];
        const float4 v = __ldg(xin + (size_t)srow[p] * WQ);
        acc.x += w * v.x; acc.y += w * v.y; acc.z += w * v.z; acc.w += w * v.w;
    }

    ((float4*)g_mid)[((size_t)bc * OH + oh) * WQ + wq] = acc;
}

// ---------------------------------------------------------------------------
// Pass 2 (taps==16): shuffle-gather. No smem, no barriers.
// Warp covers 28 outputs [28*ww, 28*ww+27] via 32 overlapping float4 loads:
// lane L loads float4 c = 28*ww + L - 2 (clamped). Interior output ow taps
// are columns [4*ow-6, 4*ow+9], contained in lanes L-2..L+2's float4s ->
// 4 float4 shuffles supply everything. Mirror-edge / non-conforming lanes
// fall back to 16 scalar global loads (L1/L2-hot, ~4 lanes per row).
// grid: (2, OH/R_P2, BC), block: 288 (9 warps; warp-chunk ww = bx*9+wid)
// ---------------------------------------------------------------------------
#define R_P2     9                    // rows per warp; 270 % 9 == 0
#define WARPS_PB 9                    // 2 blocks x 9 warps = 18 warp-chunks/row
#define OUTS_PW  28

__global__ void __launch_bounds__(288, 3)
pass2_shfl(const float* __restrict__ w_w,
           const int* __restrict__ idx_w,
           float* __restrict__ out)
{
    const int wid = threadIdx.x >> 5;
    const int L   = threadIdx.x & 31;
    const int ww  = blockIdx.x * WARPS_PB + wid;      // 0..17
    const int ow  = ww * OUTS_PW + L - 2;             // -2 .. 505
    const int bc  = blockIdx.z;
    const int oh0 = blockIdx.y * R_P2;

    const int owc = (ow < 0) ? 0 : (ow > OW - 1 ? OW - 1 : ow);

    // Per-thread tables (vectorized loads; garbage for supplier lanes, unused)
    float wreg[16];
    int   creg[16];
    {
        const float4* wp = (const float4*)(w_w + owc * 16);
        const int4*   ip = (const int4*)(idx_w + owc * 16);
#pragma unroll
        for (int j = 0; j < 4; ++j) {
            float4 wv = __ldg(wp + j);
            int4   iv = __ldg(ip + j);
            wreg[4 * j + 0] = wv.x; wreg[4 * j + 1] = wv.y;
            wreg[4 * j + 2] = wv.z; wreg[4 * j + 3] = wv.w;
            int a = iv.x, b = iv.y, cc = iv.z, d = iv.w;
            a = (a < 0) ? 0 : (a > W_IN - 1 ? W_IN - 1 : a);
            b = (b < 0) ? 0 : (b > W_IN - 1 ? W_IN - 1 : b);
            cc = (cc < 0) ? 0 : (cc > W_IN - 1 ? W_IN - 1 : cc);
            d = (d < 0) ? 0 : (d > W_IN - 1 ? W_IN - 1 : d);
            creg[4 * j + 0] = a; creg[4 * j + 1] = b;
            creg[4 * j + 2] = cc; creg[4 * j + 3] = d;
        }
    }

    const bool compute = (L >= 2) && (L <= 29) && (ow < OW);
    bool conforms = (creg[0] == 4 * ow - 6);
#pragma unroll
    for (int p = 1; p < 16; ++p)
        conforms = conforms && (creg[p] == creg[0] + p);
    const bool useShfl = compute && conforms;

    const float4* row4 = (const float4*)g_mid + ((size_t)bc * OH + oh0) * WQ + owc;
    const float*  rowf = g_mid + ((size_t)bc * OH + oh0) * (size_t)W_IN;

    float4 v = __ldg(row4);                            // row 0

#pragma unroll
    for (int r = 0; r < R_P2; ++r) {
        // Full-warp shuffles (unconditional, full mask)
        float4 am2, am1, ap1, ap2;
        am2.x = __shfl_up_sync(0xFFFFFFFFu, v.x, 2);
        am2.y = __shfl_up_sync(0xFFFFFFFFu, v.y, 2);
        am2.z = __shfl_up_sync(0xFFFFFFFFu, v.z, 2);
        am2.w = __shfl_up_sync(0xFFFFFFFFu, v.w, 2);
        am1.x = __shfl_up_sync(0xFFFFFFFFu, v.x, 1);
        am1.y = __shfl_up_sync(0xFFFFFFFFu, v.y, 1);
        am1.z = __shfl_up_sync(0xFFFFFFFFu, v.z, 1);
        am1.w = __shfl_up_sync(0xFFFFFFFFu, v.w, 1);
        ap1.x = __shfl_down_sync(0xFFFFFFFFu, v.x, 1);
        ap1.y = __shfl_down_sync(0xFFFFFFFFu, v.y, 1);
        ap1.z = __shfl_down_sync(0xFFFFFFFFu, v.z, 1);
        ap1.w = __shfl_down_sync(0xFFFFFFFFu, v.w, 1);
        ap2.x = __shfl_down_sync(0xFFFFFFFFu, v.x, 2);
        ap2.y = __shfl_down_sync(0xFFFFFFFFu, v.y, 2);
        ap2.z = __shfl_down_sync(0xFFFFFFFFu, v.z, 2);
        ap2.w = __shfl_down_sync(0xFFFFFFFFu, v.w, 2);

        // Prefetch next row (independent; latency hidden under FMA/stores)
        float4 vn = v;
        if (r + 1 < R_P2)
            vn = __ldg(row4 + (size_t)(r + 1) * WQ);

        if (compute) {
            float o;
            if (useShfl) {
                // window[2..17] of [am2|am1|v|ap1|ap2] = cols [4ow-6, 4ow+9]
                float a0 = 0.f, a1 = 0.f;
                a0 += wreg[0]  * am2.z;  a1 += wreg[1]  * am2.w;
                a0 += wreg[2]  * am1.x;  a1 += wreg[3]  * am1.y;
                a0 += wreg[4]  * am1.z;  a1 += wreg[5]  * am1.w;
                a0 += wreg[6]  * v.x;    a1 += wreg[7]  * v.y;
                a0 += wreg[8]  * v.z;    a1 += wreg[9]  * v.w;
                a0 += wreg[10] * ap1.x;  a1 += wreg[11] * ap1.y;
                a0 += wreg[12] * ap1.z;  a1 += wreg[13] * ap1.w;
                a0 += wreg[14] * ap2.x;  a1 += wreg[15] * ap2.y;
                o = a0 + a1;
            } else {
                // mirror-edge fallback: 16 scalar loads, L1/L2-hot row
                const float* rf = rowf + (size_t)r * W_IN;
                float a0 = 0.f, a1 = 0.f;
#pragma unroll
                for (int p = 0; p < 16; p += 2) {
                    a0 += wreg[p]     * __ldg(rf + creg[p]);
                    a1 += wreg[p + 1] * __ldg(rf + creg[p + 1]);
                }
                o = a0 + a1;
            }
            out[((size_t)bc * OH + oh0 + r) * OW + ow] = o;
        }
        v = vn;
    }
}

// ---------------------------------------------------------------------------
// Pass 2 generic fallback (taps != 16): R11's proven pipelined smem version.
// ---------------------------------------------------------------------------
#define R_ROWS2 9
#define SROW_SZ (W_IN + W_IN / 32)

__global__ void __launch_bounds__(480)
pass2_generic(const float* __restrict__ w_w,
              const int* __restrict__ idx_w,
              float* __restrict__ out,
              int taps)
{
    __shared__ float buf[2][SROW_SZ];

    const int t   = threadIdx.x;
    const int bc  = blockIdx.z;
    const int oh0 = blockIdx.y * R_ROWS2;

    float wreg[MAX_TAPS];
    int   preg[MAX_TAPS];
    for (int p = 0; p < taps; ++p) {
        wreg[p] = w_w[t * taps + p];
        int c = idx_w[t * taps + p];
        c = (c < 0) ? 0 : (c > W_IN - 1 ? W_IN - 1 : c);
        preg[p] = c + (c >> 5);
    }

    const int c0   = t * 4;
    const int base = c0 + (c0 >> 5);
    const float4* rows = (const float4*)g_mid + ((size_t)bc * OH + oh0) * WQ + t;

    float4 v = __ldg(rows);
    for (int r = 0; r < R_ROWS2; ++r) {
        float* cur = buf[r & 1];
        cur[base + 0] = v.x; cur[base + 1] = v.y;
        cur[base + 2] = v.z; cur[base + 3] = v.w;
        __syncthreads();
        if (r + 1 < R_ROWS2)
            v = __ldg(rows + (size_t)(r + 1) * WQ);
        float acc = 0.f;
        for (int p = 0; p < taps; ++p)
            acc += wreg[p] * cur[preg[p]];
        out[((size_t)bc * OH + oh0 + r) * OW + t] = acc;
    }
}

// ---------------------------------------------------------------------------
// kernel_launch
// inputs: x(f32), w_h(f32), idx_h(i32), w_w(f32), idx_w(i32); output f32
// ---------------------------------------------------------------------------
extern "C" void kernel_launch(void* const* d_in, const int* in_sizes, int n_in,
                              void* d_out, int out_size)
{
    const float* x     = (const float*)d_in[0];
    const float* w_h   = (const float*)d_in[1];
    const int*   idx_h = (const int*)d_in[2];
    const float* w_w   = (const float*)d_in[3];
    const int*   idx_w = (const int*)d_in[4];
    float*       out   = (float*)d_out;

    int taps_h = in_sizes[1] / OH;
    int taps_w = in_sizes[3] / OW;
    if (taps_h > MAX_TAPS) taps_h = MAX_TAPS;
    if (taps_w > MAX_TAPS) taps_w = MAX_TAPS;

    {
        dim3 grid((WQ + 127) / 128, OH, BC);   // (4, 270, 24)
        if (taps_h == 16)
            pass1_vert<16><<<grid, 128>>>(x, w_h, idx_h, taps_h);
        else
            pass1_vert<0><<<grid, 128>>>(x, w_h, idx_h, taps_h);
    }
    if (taps_w == 16) {
        dim3 grid(2, OH / R_P2, BC);           // (2, 30, 24) = 1440 blocks
        pass2_shfl<<<grid, 288>>>(w_w, idx_w, out);
    } else {
        dim3 grid(1, OH / R_ROWS2, BC);
        pass2_generic<<<grid, 480>>>(w_w, idx_w, out, taps_w);
    }
}